// round 8
// baseline (speedup 1.0000x reference)
#include <cuda_runtime.h>

#define KTAGS 48
#define PF 6
#define L2E 1.4426950408889634f
#define LN2 0.6931471805599453f

#define MAXB 4096
__device__ float g_wf[MAXB * KTAGS];
__device__ float g_wb[MAXB * KTAGS];
__device__ float g_c2f[MAXB];
__device__ float g_c2b[MAXB];
__device__ float g_path[MAXB];

__device__ __forceinline__ unsigned long long pk2(float lo, float hi) {
    unsigned long long r;
    asm("mov.b64 %0,{%1,%2};" : "=l"(r) : "f"(lo), "f"(hi));
    return r;
}
__device__ __forceinline__ void unpk2(unsigned long long v, float& a, float& b) {
    asm("mov.b64 {%0,%1},%2;" : "=f"(a), "=f"(b) : "l"(v));
}
__device__ __forceinline__ unsigned long long ffma2(unsigned long long a, unsigned long long b,
                                                    unsigned long long c) {
    unsigned long long d;
    asm("fma.rn.f32x2 %0,%1,%2,%3;" : "=l"(d) : "l"(a), "l"(b), "l"(c));
    return d;
}
__device__ __forceinline__ unsigned long long fadd2(unsigned long long a, unsigned long long b) {
    unsigned long long d;
    asm("add.rn.f32x2 %0,%1,%2;" : "=l"(d) : "l"(a), "l"(b));
    return d;
}
__device__ __forceinline__ float ex2f(float x) {
    float r; asm("ex2.approx.f32 %0,%1;" : "=f"(r) : "f"(x)); return r;
}
__device__ __forceinline__ float lg2f(float x) {
    float r; asm("lg2.approx.f32 %0,%1;" : "=f"(r) : "f"(x)); return r;
}
__device__ __forceinline__ float rcpf(float x) {
    float r; asm("rcp.approx.f32 %0,%1;" : "=f"(r) : "f"(x)); return r;
}

__device__ __forceinline__ void matvec48(const unsigned long long* MA,
                                         const unsigned long long* MB,
                                         const float* svp,
                                         float& outA, float& outB) {
    const ulonglong2* vv = (const ulonglong2*)svp;
    unsigned long long a0 = pk2(0.0f, 0.0f), a1 = a0, a2 = a0, a3 = a0;
    unsigned long long b0 = a0, b1 = a0, b2 = a0, b3 = a0;
#pragma unroll
    for (int q = 0; q < 12; q += 2) {
        ulonglong2 x0 = vv[q];
        ulonglong2 x1 = vv[q + 1];
        a0 = ffma2(MA[2 * q],     x0.x, a0);
        b0 = ffma2(MB[2 * q],     x0.x, b0);
        a1 = ffma2(MA[2 * q + 1], x0.y, a1);
        b1 = ffma2(MB[2 * q + 1], x0.y, b1);
        a2 = ffma2(MA[2 * q + 2], x1.x, a2);
        b2 = ffma2(MB[2 * q + 2], x1.x, b2);
        a3 = ffma2(MA[2 * q + 3], x1.y, a3);
        b3 = ffma2(MB[2 * q + 3], x1.y, b3);
    }
    unsigned long long sA = fadd2(fadd2(a0, a1), fadd2(a2, a3));
    unsigned long long sB = fadd2(fadd2(b0, b1), fadd2(b2, b3));
    float alo, ahi, blo, bhi;
    unpk2(sA, alo, ahi);
    unpk2(sB, blo, bhi);
    outA = alo + ahi;
    outB = blo + bhi;
}

// Bidirectional CRF with TWO batch columns per single-warp CTA, interleaved in
// one straight-line step body (shared E registers, one syncwarp per step).
// CTAs [0, B/2): forward alpha 0..m for pair (2q, 2q+1).
// CTAs [B/2, B): backward beta L-1..m for the same pair.
__global__ void __launch_bounds__(32) crf_bidir(
    const float* __restrict__ emis,   // [B, T, K]
    const int* __restrict__ lengths,  // [B]
    const int* __restrict__ tags,     // [B, T]
    const float* __restrict__ prior,  // [K]
    const float* __restrict__ trans,  // [K, K]
    const float* __restrict__ ftrans, // [K]
    int B2, int T)
{
    __shared__ __align__(16) float sv0[KTAGS];
    __shared__ __align__(16) float sv1[KTAGS];

    const bool fwd = (blockIdx.x < (unsigned)B2);
    const int pairid = fwd ? blockIdx.x : (blockIdx.x - B2);
    const int b0 = 2 * pairid, b1 = b0 + 1;
    const int j = threadIdx.x;
    const bool hB = (j < 16);
    const int rA = j;
    const int rB = 32 + (j & 15);

    int L0 = lengths[b0]; L0 = L0 < 1 ? 1 : (L0 > T ? T : L0);
    int L1 = lengths[b1]; L1 = L1 < 1 ? 1 : (L1 > T ? T : L1);
    const int m0 = L0 >> 1, m1 = L1 >> 1;

    const float* eb0 = emis + (size_t)b0 * T * KTAGS;
    const float* eb1 = emis + (size_t)b1 * T * KTAGS;

    unsigned long long EA[24], EB[24];
    if (fwd) {
        // EA[q] packs exp(trans[rA][2q]), exp(trans[rA][2q+1])
        const float4* trA = (const float4*)(trans + rA * KTAGS);
        const float4* trB = (const float4*)(trans + rB * KTAGS);
#pragma unroll
        for (int q = 0; q < 12; q++) {
            float4 va = trA[q];
            EA[2 * q]     = pk2(ex2f(va.x * L2E), ex2f(va.y * L2E));
            EA[2 * q + 1] = pk2(ex2f(va.z * L2E), ex2f(va.w * L2E));
            float4 vb4 = trB[q];
            EB[2 * q]     = pk2(ex2f(vb4.x * L2E), ex2f(vb4.y * L2E));
            EB[2 * q + 1] = pk2(ex2f(vb4.z * L2E), ex2f(vb4.w * L2E));
        }
    } else {
        // Transposed: EA[q] packs exp(trans[2q][rA]), exp(trans[2q+1][rA])
#pragma unroll
        for (int q = 0; q < 24; q++) {
            int j0 = 2 * q, j1 = 2 * q + 1;
            EA[q] = pk2(ex2f(trans[j0 * KTAGS + rA] * L2E),
                        ex2f(trans[j1 * KTAGS + rA] * L2E));
            EB[q] = pk2(ex2f(trans[j0 * KTAGS + rB] * L2E),
                        ex2f(trans[j1 * KTAGS + rB] * L2E));
        }
    }

    if (fwd) {
        // ---------- forward half ----------
        float aA0 = eb0[rA] + prior[rA], aB0 = eb0[rB] + prior[rB];
        float aA1 = eb1[rA] + prior[rA], aB1 = eb1[rB] + prior[rB];
        float mm0 = __shfl_sync(0xffffffffu, aA0, 0);
        float mm1 = __shfl_sync(0xffffffffu, aA1, 0);
        float C20 = mm0 * L2E, C21 = mm1 * L2E;
        float wA0 = ex2f((aA0 - mm0) * L2E), wB0 = ex2f((aB0 - mm0) * L2E);
        float wA1 = ex2f((aA1 - mm1) * L2E), wB1 = ex2f((aB1 - mm1) * L2E);
        sv0[rA] = wA0; if (hB) sv0[rB] = wB0;
        sv1[rA] = wA1; if (hB) sv1[rB] = wB1;
        __syncwarp();

        float r0A[PF], r0B[PF], r1A[PF], r1B[PF];
#pragma unroll
        for (int d = 0; d < PF; d++) {
            int t = 1 + d;
            r0A[d] = (t <= m0) ? eb0[(size_t)t * KTAGS + rA] : 0.0f;
            r0B[d] = (t <= m0 && hB) ? eb0[(size_t)t * KTAGS + rB] : 0.0f;
            r1A[d] = (t <= m1) ? eb1[(size_t)t * KTAGS + rA] : 0.0f;
            r1B[d] = (t <= m1 && hB) ? eb1[(size_t)t * KTAGS + rB] : 0.0f;
        }

        const int kmax = m0 > m1 ? m0 : m1;
        for (int k0 = 1; k0 <= kmax; k0 += PF) {
#pragma unroll
            for (int d = 0; d < PF; d++) {
                const int k = k0 + d;
                if (k > kmax) break;

                float rr0 = __shfl_sync(0xffffffffu, wA0, 0);
                float rr1 = __shfl_sync(0xffffffffu, wA1, 0);
                float g0 = rcpf(rr0), g1 = rcpf(rr1);
                float eA0 = ex2f(r0A[d] * L2E), eB0 = ex2f(r0B[d] * L2E);
                float eA1 = ex2f(r1A[d] * L2E), eB1 = ex2f(r1B[d] * L2E);
                {
                    int tn = k + PF;
                    r0A[d] = (tn <= m0) ? eb0[(size_t)tn * KTAGS + rA] : 0.0f;
                    r0B[d] = (tn <= m0 && hB) ? eb0[(size_t)tn * KTAGS + rB] : 0.0f;
                    r1A[d] = (tn <= m1) ? eb1[(size_t)tn * KTAGS + rA] : 0.0f;
                    r1B[d] = (tn <= m1 && hB) ? eb1[(size_t)tn * KTAGS + rB] : 0.0f;
                }

                float uA0, uB0, uA1, uB1;
                matvec48(EA, EB, sv0, uA0, uB0);
                matvec48(EA, EB, sv1, uA1, uB1);

                if (k <= m0) {
                    wA0 = uA0 * (eA0 * g0);
                    wB0 = uB0 * (eB0 * g0);
                    C20 += lg2f(rr0);
                    sv0[rA] = wA0; if (hB) sv0[rB] = wB0;
                }
                if (k <= m1) {
                    wA1 = uA1 * (eA1 * g1);
                    wB1 = uB1 * (eB1 * g1);
                    C21 += lg2f(rr1);
                    sv1[rA] = wA1; if (hB) sv1[rB] = wB1;
                }
                __syncwarp();
            }
        }

        g_wf[b0 * KTAGS + rA] = wA0; if (hB) g_wf[b0 * KTAGS + rB] = wB0;
        g_wf[b1 * KTAGS + rA] = wA1; if (hB) g_wf[b1 * KTAGS + rB] = wB1;
        if (j == 0) { g_c2f[b0] = C20; g_c2f[b1] = C21; }

        // ---- path scores (both columns) ----
        const int* tb0 = tags + (size_t)b0 * T;
        const int* tb1 = tags + (size_t)b1 * T;
        float acc0 = 0.0f, acc1 = 0.0f;
        for (int t = j; t < L0; t += 32) {
            int tg = min(max(tb0[t], 0), KTAGS - 1);
            float tr = (t == 0) ? prior[tg]
                                : trans[tg * KTAGS + min(max(tb0[t - 1], 0), KTAGS - 1)];
            acc0 += eb0[(size_t)t * KTAGS + tg] + tr;
        }
        for (int t = j; t < L1; t += 32) {
            int tg = min(max(tb1[t], 0), KTAGS - 1);
            float tr = (t == 0) ? prior[tg]
                                : trans[tg * KTAGS + min(max(tb1[t - 1], 0), KTAGS - 1)];
            acc1 += eb1[(size_t)t * KTAGS + tg] + tr;
        }
#pragma unroll
        for (int s = 16; s > 0; s >>= 1) {
            acc0 += __shfl_xor_sync(0xffffffffu, acc0, s);
            acc1 += __shfl_xor_sync(0xffffffffu, acc1, s);
        }
        if (j == 0) {
            g_path[b0] = acc0 + ftrans[min(max(tb0[L0 - 1], 0), KTAGS - 1)];
            g_path[b1] = acc1 + ftrans[min(max(tb1[L1 - 1], 0), KTAGS - 1)];
        }
    } else {
        // ---------- backward half: beta_t = E^T (exp(e_{t+1}) . beta_{t+1}) ----------
        float zA0 = ex2f(ftrans[rA] * L2E), zB0 = ex2f(ftrans[rB] * L2E);
        float zA1 = zA0, zB1 = zB0;
        float C20 = 0.0f, C21 = 0.0f;
        const int nb0 = L0 - 1 - m0, nb1 = L1 - 1 - m1;
        const int nbmax = nb0 > nb1 ? nb0 : nb1;

        float r0A[PF], r0B[PF], r1A[PF], r1B[PF];
#pragma unroll
        for (int d = 0; d < PF; d++) {
            r0A[d] = (d < nb0) ? eb0[(size_t)(L0 - 1 - d) * KTAGS + rA] : 0.0f;
            r0B[d] = (d < nb0 && hB) ? eb0[(size_t)(L0 - 1 - d) * KTAGS + rB] : 0.0f;
            r1A[d] = (d < nb1) ? eb1[(size_t)(L1 - 1 - d) * KTAGS + rA] : 0.0f;
            r1B[d] = (d < nb1 && hB) ? eb1[(size_t)(L1 - 1 - d) * KTAGS + rB] : 0.0f;
        }

        for (int s0 = 0; s0 < nbmax; s0 += PF) {
#pragma unroll
            for (int d = 0; d < PF; d++) {
                const int s = s0 + d;
                if (s >= nbmax) break;

                float rr0 = __shfl_sync(0xffffffffu, zA0, 0);
                float rr1 = __shfl_sync(0xffffffffu, zA1, 0);
                float g0 = rcpf(rr0), g1 = rcpf(rr1);
                float eA0 = ex2f(r0A[d] * L2E), eB0 = ex2f(r0B[d] * L2E);
                float eA1 = ex2f(r1A[d] * L2E), eB1 = ex2f(r1B[d] * L2E);
                {
                    int sn = s + PF;
                    r0A[d] = (sn < nb0) ? eb0[(size_t)(L0 - 1 - sn) * KTAGS + rA] : 0.0f;
                    r0B[d] = (sn < nb0 && hB) ? eb0[(size_t)(L0 - 1 - sn) * KTAGS + rB] : 0.0f;
                    r1A[d] = (sn < nb1) ? eb1[(size_t)(L1 - 1 - sn) * KTAGS + rA] : 0.0f;
                    r1B[d] = (sn < nb1 && hB) ? eb1[(size_t)(L1 - 1 - sn) * KTAGS + rB] : 0.0f;
                }

                const bool a0 = (s < nb0), a1 = (s < nb1);
                if (a0) {
                    sv0[rA] = zA0 * (eA0 * g0);
                    if (hB) sv0[rB] = zB0 * (eB0 * g0);
                    C20 += lg2f(rr0);
                }
                if (a1) {
                    sv1[rA] = zA1 * (eA1 * g1);
                    if (hB) sv1[rB] = zB1 * (eB1 * g1);
                    C21 += lg2f(rr1);
                }
                __syncwarp();

                float uA0, uB0, uA1, uB1;
                matvec48(EA, EB, sv0, uA0, uB0);
                matvec48(EA, EB, sv1, uA1, uB1);
                if (a0) { zA0 = uA0; zB0 = uB0; }
                if (a1) { zA1 = uA1; zB1 = uB1; }
            }
        }

        g_wb[b0 * KTAGS + rA] = zA0; if (hB) g_wb[b0 * KTAGS + rB] = zB0;
        g_wb[b1 * KTAGS + rA] = zA1; if (hB) g_wb[b1 * KTAGS + rB] = zB1;
        if (j == 0) { g_c2b[b0] = C20; g_c2b[b1] = C21; }
    }
}

// Warp-per-batch combine: coalesced dot(alpha_m, beta_m) + mean.
__global__ void crf_reduce(float* __restrict__ out, int B) {
    __shared__ float sh[16];
    const int tid = threadIdx.x;
    const int u = tid >> 5, j = tid & 31;
    float v = 0.0f;
    for (int b = u; b < B; b += 16) {
        float d = g_wf[b * KTAGS + j] * g_wb[b * KTAGS + j];
        if (j < 16) d += g_wf[b * KTAGS + 32 + j] * g_wb[b * KTAGS + 32 + j];
#pragma unroll
        for (int s = 16; s > 0; s >>= 1) d += __shfl_xor_sync(0xffffffffu, d, s);
        if (j == 0)
            v += (lg2f(d) + g_c2f[b] + g_c2b[b]) * LN2 - g_path[b];
    }
    if (j == 0) sh[u] = v;
    __syncthreads();
    if (tid == 0) {
        float s = 0.0f;
#pragma unroll
        for (int k = 0; k < 16; k++) s += sh[k];
        out[0] = s / (float)B;
    }
}

extern "C" void kernel_launch(void* const* d_in, const int* in_sizes, int n_in,
                              void* d_out, int out_size) {
    const float* emis    = (const float*)d_in[0];
    const int*   lengths = (const int*)d_in[1];
    const int*   tags    = (const int*)d_in[2];
    const float* prior   = (const float*)d_in[3];
    const float* trans   = (const float*)d_in[4];
    const float* ftrans  = (const float*)d_in[5];

    const int B = in_sizes[1];              // lengths count
    const int T = in_sizes[2] / B;          // tags = [B, T]

    crf_bidir<<<B, 32>>>(emis, lengths, tags, prior, trans, ftrans, B / 2, T);
    crf_reduce<<<1, 512>>>((float*)d_out, B);
}

// round 9
// speedup vs baseline: 2.1459x; 2.1459x over previous
#include <cuda_runtime.h>

#define KTAGS 48
#define PF 8
#define L2E 1.4426950408889634f
#define LN2 0.6931471805599453f

#define MAXB 4096
__device__ float g_wf[MAXB * KTAGS];
__device__ float g_wb[MAXB * KTAGS];
__device__ float g_c2f[MAXB];
__device__ float g_c2b[MAXB];
__device__ float g_path[MAXB];
__device__ float g_partial[64];

__device__ __forceinline__ unsigned long long pk2(float lo, float hi) {
    unsigned long long r;
    asm("mov.b64 %0,{%1,%2};" : "=l"(r) : "f"(lo), "f"(hi));
    return r;
}
__device__ __forceinline__ void unpk2(unsigned long long v, float& a, float& b) {
    asm("mov.b64 {%0,%1},%2;" : "=f"(a), "=f"(b) : "l"(v));
}
__device__ __forceinline__ unsigned long long ffma2(unsigned long long a, unsigned long long b,
                                                    unsigned long long c) {
    unsigned long long d;
    asm("fma.rn.f32x2 %0,%1,%2,%3;" : "=l"(d) : "l"(a), "l"(b), "l"(c));
    return d;
}
__device__ __forceinline__ unsigned long long fadd2(unsigned long long a, unsigned long long b) {
    unsigned long long d;
    asm("add.rn.f32x2 %0,%1,%2;" : "=l"(d) : "l"(a), "l"(b));
    return d;
}
__device__ __forceinline__ float ex2f(float x) {
    float r; asm("ex2.approx.f32 %0,%1;" : "=f"(r) : "f"(x)); return r;
}
__device__ __forceinline__ float lg2f(float x) {
    float r; asm("lg2.approx.f32 %0,%1;" : "=f"(r) : "f"(x)); return r;
}
__device__ __forceinline__ float rcpf(float x) {
    float r; asm("rcp.approx.f32 %0,%1;" : "=f"(r) : "f"(x)); return r;
}

__device__ __forceinline__ void matvec48(const unsigned long long* MA,
                                         const unsigned long long* MB,
                                         const float* svp,
                                         float& outA, float& outB) {
    const ulonglong2* vv = (const ulonglong2*)svp;
    unsigned long long a0 = pk2(0.0f, 0.0f), a1 = a0, a2 = a0, a3 = a0;
    unsigned long long b0 = a0, b1 = a0, b2 = a0, b3 = a0;
#pragma unroll
    for (int q = 0; q < 12; q += 2) {
        ulonglong2 x0 = vv[q];
        ulonglong2 x1 = vv[q + 1];
        a0 = ffma2(MA[2 * q],     x0.x, a0);
        b0 = ffma2(MB[2 * q],     x0.x, b0);
        a1 = ffma2(MA[2 * q + 1], x0.y, a1);
        b1 = ffma2(MB[2 * q + 1], x0.y, b1);
        a2 = ffma2(MA[2 * q + 2], x1.x, a2);
        b2 = ffma2(MB[2 * q + 2], x1.x, b2);
        a3 = ffma2(MA[2 * q + 3], x1.y, a3);
        b3 = ffma2(MB[2 * q + 3], x1.y, b3);
    }
    unsigned long long sA = fadd2(fadd2(a0, a1), fadd2(a2, a3));
    unsigned long long sB = fadd2(fadd2(b0, b1), fadd2(b2, b3));
    float alo, ahi, blo, bhi;
    unpk2(sA, alo, ahi);
    unpk2(sB, blo, bhi);
    outA = alo + ahi;
    outB = blo + bhi;
}

// Bidirectional CRF: CTAs [0,B) forward alpha 0..m, CTAs [B,2B) backward beta
// L-1..m (m = L/2). Single warp per CTA; syncwarp per step; linear domain.
// Renormalization only every 4th step (growth bounded ~2^12/step, fp32-safe);
// C2 accumulates lg2 of exactly what is divided out, so logZ stays exact.
__global__ void __launch_bounds__(32) crf_bidir(
    const float* __restrict__ emis,   // [B, T, K]
    const int* __restrict__ lengths,  // [B]
    const int* __restrict__ tags,     // [B, T]
    const float* __restrict__ prior,  // [K]
    const float* __restrict__ trans,  // [K, K]
    const float* __restrict__ ftrans, // [K]
    int B, int T)
{
    __shared__ __align__(16) float sv[2][KTAGS];

    const bool fwd = (blockIdx.x < (unsigned)B);
    const int b = fwd ? blockIdx.x : (blockIdx.x - B);
    const int j = threadIdx.x;
    const bool hB = (j < 16);
    const int rA = j;
    const int rB = 32 + (j & 15);

    int L = lengths[b];
    if (L < 1) L = 1;
    if (L > T) L = T;
    const int m = L >> 1;

    const float* eb = emis + (size_t)b * T * KTAGS;

    if (fwd) {
        unsigned long long EA[24], EB[24];
        {
            const float4* trA = (const float4*)(trans + rA * KTAGS);
            const float4* trB = (const float4*)(trans + rB * KTAGS);
#pragma unroll
            for (int q = 0; q < 12; q++) {
                float4 va = trA[q];
                EA[2 * q]     = pk2(ex2f(va.x * L2E), ex2f(va.y * L2E));
                EA[2 * q + 1] = pk2(ex2f(va.z * L2E), ex2f(va.w * L2E));
                float4 vb4 = trB[q];
                EB[2 * q]     = pk2(ex2f(vb4.x * L2E), ex2f(vb4.y * L2E));
                EB[2 * q + 1] = pk2(ex2f(vb4.z * L2E), ex2f(vb4.w * L2E));
            }
        }

        float aA = eb[rA] + prior[rA];
        float aB = eb[rB] + prior[rB];
        float m0 = __shfl_sync(0xffffffffu, aA, 0);
        float C2 = m0 * L2E;
        float wA = ex2f((aA - m0) * L2E);
        float wB = ex2f((aB - m0) * L2E);
        sv[0][rA] = wA;
        if (hB) sv[0][rB] = wB;
        __syncwarp();
        int p = 0;

        const int Lf = m + 1;
        float rawA[PF], rawB[PF];
#pragma unroll
        for (int d = 0; d < PF; d++) {
            int t = 1 + d;
            rawA[d] = (t < Lf) ? eb[(size_t)t * KTAGS + rA] : 0.0f;
            rawB[d] = (t < Lf && hB) ? eb[(size_t)t * KTAGS + rB] : 0.0f;
        }

        for (int t0 = 1; t0 < Lf; t0 += PF) {
#pragma unroll
            for (int d = 0; d < PF; d++) {
                const int t = t0 + d;
                if (t >= Lf) break;

                float eetA = ex2f(rawA[d] * L2E);
                float eetB = ex2f(rawB[d] * L2E);
                {
                    int tn = t + PF;
                    rawA[d] = (tn < Lf) ? eb[(size_t)tn * KTAGS + rA] : 0.0f;
                    rawB[d] = (tn < Lf && hB) ? eb[(size_t)tn * KTAGS + rB] : 0.0f;
                }

                float gA = eetA, gB = eetB;
                if ((d & 3) == 0) {  // renorm step (compile-time branch in unroll)
                    float r = __shfl_sync(0xffffffffu, wA, 0);
                    float rr = rcpf(r);
                    C2 += lg2f(r);
                    gA = eetA * rr;
                    gB = eetB * rr;
                }

                float uA, uB;
                matvec48(EA, EB, sv[p], uA, uB);
                wA = uA * gA;
                wB = uB * gB;

                const int q2 = p ^ 1;
                sv[q2][rA] = wA;
                if (hB) sv[q2][rB] = wB;
                __syncwarp();
                p = q2;
            }
        }

        g_wf[b * KTAGS + rA] = wA;
        if (hB) g_wf[b * KTAGS + rB] = wB;
        if (j == 0) g_c2f[b] = C2;

        // ---- path score over full L ----
        const int* tb = tags + (size_t)b * T;
        float acc = 0.0f;
        for (int t = j; t < L; t += 32) {
            int tg = min(max(tb[t], 0), KTAGS - 1);
            float tr = (t == 0) ? prior[tg]
                                : trans[tg * KTAGS + min(max(tb[t - 1], 0), KTAGS - 1)];
            acc += eb[(size_t)t * KTAGS + tg] + tr;
        }
#pragma unroll
        for (int s = 16; s > 0; s >>= 1)
            acc += __shfl_xor_sync(0xffffffffu, acc, s);
        if (j == 0)
            g_path[b] = acc + ftrans[min(max(tb[L - 1], 0), KTAGS - 1)];
    } else {
        // Backward: beta_t = E^T (exp(e_{t+1}) . beta_{t+1})
        unsigned long long EA[24], EB[24];
#pragma unroll
        for (int q = 0; q < 24; q++) {
            int j0 = 2 * q, j1 = 2 * q + 1;
            EA[q] = pk2(ex2f(trans[j0 * KTAGS + rA] * L2E),
                        ex2f(trans[j1 * KTAGS + rA] * L2E));
            EB[q] = pk2(ex2f(trans[j0 * KTAGS + rB] * L2E),
                        ex2f(trans[j1 * KTAGS + rB] * L2E));
        }

        float C2 = 0.0f;
        float vbA, vbB;

        if (m == L - 1) {
            vbA = ex2f(ftrans[rA] * L2E);
            vbB = ex2f(ftrans[rB] * L2E);
        } else {
            float zA = ex2f((ftrans[rA] + eb[(size_t)(L - 1) * KTAGS + rA]) * L2E);
            float zB = ex2f((ftrans[rB] + eb[(size_t)(L - 1) * KTAGS + rB]) * L2E);
            sv[0][rA] = zA;
            if (hB) sv[0][rB] = zB;
            __syncwarp();
            int p = 0;

            const int nsteps = L - 1 - m;
            const int nfull = nsteps - 1;

            float rawA[PF], rawB[PF];
#pragma unroll
            for (int d = 0; d < PF; d++) {
                int t = L - 2 - d;
                rawA[d] = (d < nfull) ? eb[(size_t)t * KTAGS + rA] : 0.0f;
                rawB[d] = (d < nfull && hB) ? eb[(size_t)t * KTAGS + rB] : 0.0f;
            }

            for (int s0 = 0; s0 < nfull; s0 += PF) {
#pragma unroll
                for (int d = 0; d < PF; d++) {
                    const int s = s0 + d;
                    if (s >= nfull) break;
                    const int t = L - 2 - s;

                    float eetA = ex2f(rawA[d] * L2E);
                    float eetB = ex2f(rawB[d] * L2E);
                    {
                        int sn = s + PF;
                        int tn = t - PF;
                        rawA[d] = (sn < nfull) ? eb[(size_t)tn * KTAGS + rA] : 0.0f;
                        rawB[d] = (sn < nfull && hB) ? eb[(size_t)tn * KTAGS + rB] : 0.0f;
                    }

                    float gA = eetA, gB = eetB;
                    if ((d & 3) == 0) {
                        float r = __shfl_sync(0xffffffffu, zA, 0);
                        float rr = rcpf(r);
                        C2 += lg2f(r);
                        gA = eetA * rr;
                        gB = eetB * rr;
                    }

                    // matvec on current buffer, then store scaled next state
                    float uA, uB;
                    {
                        // fold emission/renorm into the stored operand:
                        // store z*g first, sync, then matvec reads it.
                        sv[p ^ 1][rA] = zA * gA;
                        if (hB) sv[p ^ 1][rB] = zB * gB;
                        __syncwarp();
                        matvec48(EA, EB, sv[p ^ 1], uA, uB);
                    }
                    zA = uA;
                    zB = uB;
                    p ^= 1;
                }
            }
            // Final step (t = m): matvec only — operand is raw z (no emission).
            sv[p ^ 1][rA] = zA;
            if (hB) sv[p ^ 1][rB] = zB;
            __syncwarp();
            matvec48(EA, EB, sv[p ^ 1], vbA, vbB);
        }

        g_wb[b * KTAGS + rA] = vbA;
        if (hB) g_wb[b * KTAGS + rB] = vbB;
        if (j == 0) g_c2b[b] = C2;
    }
}

// Parallel combine: one warp per batch iteration; 32 blocks x 256 threads.
__global__ void crf_combine(int B) {
    __shared__ float sh[8];
    const int tid = threadIdx.x;
    const int wid = tid >> 5, j = tid & 31;
    const int gw = blockIdx.x * 8 + wid;       // global warp id, 256 total
    float v = 0.0f;
    for (int b = gw; b < B; b += 256) {
        float d = g_wf[b * KTAGS + j] * g_wb[b * KTAGS + j];
        if (j < 16) d += g_wf[b * KTAGS + 32 + j] * g_wb[b * KTAGS + 32 + j];
#pragma unroll
        for (int s = 16; s > 0; s >>= 1) d += __shfl_xor_sync(0xffffffffu, d, s);
        if (j == 0)
            v += (lg2f(d) + g_c2f[b] + g_c2b[b]) * LN2 - g_path[b];
    }
    if (j == 0) sh[wid] = v;
    __syncthreads();
    if (tid == 0) {
        float s = 0.0f;
#pragma unroll
        for (int k = 0; k < 8; k++) s += sh[k];
        g_partial[blockIdx.x] = s;
    }
}

__global__ void crf_final(float* __restrict__ out, int B) {
    const int j = threadIdx.x;
    float v = g_partial[j];
#pragma unroll
    for (int s = 16; s > 0; s >>= 1) v += __shfl_xor_sync(0xffffffffu, v, s);
    if (j == 0) out[0] = v / (float)B;
}

extern "C" void kernel_launch(void* const* d_in, const int* in_sizes, int n_in,
                              void* d_out, int out_size) {
    const float* emis    = (const float*)d_in[0];
    const int*   lengths = (const int*)d_in[1];
    const int*   tags    = (const int*)d_in[2];
    const float* prior   = (const float*)d_in[3];
    const float* trans   = (const float*)d_in[4];
    const float* ftrans  = (const float*)d_in[5];

    const int B = in_sizes[1];              // lengths count
    const int T = in_sizes[2] / B;          // tags = [B, T]

    crf_bidir<<<2 * B, 32>>>(emis, lengths, tags, prior, trans, ftrans, B, T);
    crf_combine<<<32, 256>>>(B);
    crf_final<<<1, 32>>>((float*)d_out, B);
}

// round 10
// speedup vs baseline: 2.4834x; 1.1573x over previous
#include <cuda_runtime.h>

#define KTAGS 48
#define PF 8
#define L2E 1.4426950408889634f
#define LN2 0.6931471805599453f

#define MAXB 4096
__device__ float g_wf[MAXB * KTAGS];
__device__ float g_wb[MAXB * KTAGS];
__device__ float g_c2f[MAXB];
__device__ float g_c2b[MAXB];
__device__ float g_path[MAXB];
__device__ float g_partial[64];

__device__ __forceinline__ unsigned long long pk2(float lo, float hi) {
    unsigned long long r;
    asm("mov.b64 %0,{%1,%2};" : "=l"(r) : "f"(lo), "f"(hi));
    return r;
}
__device__ __forceinline__ void unpk2(unsigned long long v, float& a, float& b) {
    asm("mov.b64 {%0,%1},%2;" : "=f"(a), "=f"(b) : "l"(v));
}
__device__ __forceinline__ unsigned long long ffma2(unsigned long long a, unsigned long long b,
                                                    unsigned long long c) {
    unsigned long long d;
    asm("fma.rn.f32x2 %0,%1,%2,%3;" : "=l"(d) : "l"(a), "l"(b), "l"(c));
    return d;
}
__device__ __forceinline__ unsigned long long fadd2(unsigned long long a, unsigned long long b) {
    unsigned long long d;
    asm("add.rn.f32x2 %0,%1,%2;" : "=l"(d) : "l"(a), "l"(b));
    return d;
}
__device__ __forceinline__ float ex2f(float x) {
    float r; asm("ex2.approx.f32 %0,%1;" : "=f"(r) : "f"(x)); return r;
}
__device__ __forceinline__ float lg2f(float x) {
    float r; asm("lg2.approx.f32 %0,%1;" : "=f"(r) : "f"(x)); return r;
}
__device__ __forceinline__ float rcpf(float x) {
    float r; asm("rcp.approx.f32 %0,%1;" : "=f"(r) : "f"(x)); return r;
}

__device__ __forceinline__ void matvec48(const unsigned long long* MA,
                                         const unsigned long long* MB,
                                         const float* svp,
                                         float& outA, float& outB) {
    const ulonglong2* vv = (const ulonglong2*)svp;
    unsigned long long a0 = pk2(0.0f, 0.0f), a1 = a0, a2 = a0, a3 = a0;
    unsigned long long b0 = a0, b1 = a0, b2 = a0, b3 = a0;
#pragma unroll
    for (int q = 0; q < 12; q += 2) {
        ulonglong2 x0 = vv[q];
        ulonglong2 x1 = vv[q + 1];
        a0 = ffma2(MA[2 * q],     x0.x, a0);
        b0 = ffma2(MB[2 * q],     x0.x, b0);
        a1 = ffma2(MA[2 * q + 1], x0.y, a1);
        b1 = ffma2(MB[2 * q + 1], x0.y, b1);
        a2 = ffma2(MA[2 * q + 2], x1.x, a2);
        b2 = ffma2(MB[2 * q + 2], x1.x, b2);
        a3 = ffma2(MA[2 * q + 3], x1.y, a3);
        b3 = ffma2(MB[2 * q + 3], x1.y, b3);
    }
    unsigned long long sA = fadd2(fadd2(a0, a1), fadd2(a2, a3));
    unsigned long long sB = fadd2(fadd2(b0, b1), fadd2(b2, b3));
    float alo, ahi, blo, bhi;
    unpk2(sA, alo, ahi);
    unpk2(sB, blo, bhi);
    outA = alo + ahi;
    outB = blo + bhi;
}

// Bidirectional CRF: CTAs [0,B) forward alpha 0..m, CTAs [B,2B) backward beta
// L-1..m (m = L/2). Single warp per CTA; syncwarp per step; linear domain;
// renorm every 4th step. Hot loop is branch-free full PF-blocks with
// immediate-offset refills; short predicated tail handles the remainder.
__global__ void __launch_bounds__(32) crf_bidir(
    const float* __restrict__ emis,   // [B, T, K]
    const int* __restrict__ lengths,  // [B]
    const int* __restrict__ tags,     // [B, T]
    const float* __restrict__ prior,  // [K]
    const float* __restrict__ trans,  // [K, K]
    const float* __restrict__ ftrans, // [K]
    int B, int T)
{
    __shared__ __align__(16) float sv[2][KTAGS];

    const bool fwd = (blockIdx.x < (unsigned)B);
    const int b = fwd ? blockIdx.x : (blockIdx.x - B);
    const int j = threadIdx.x;
    const bool hB = (j < 16);
    const int rA = j;
    const int rB = 32 + (j & 15);

    int L = lengths[b];
    if (L < 1) L = 1;
    if (L > T) L = T;
    const int m = L >> 1;

    const float* eb = emis + (size_t)b * T * KTAGS;

    if (fwd) {
        unsigned long long EA[24], EB[24];
        {
            const float4* trA = (const float4*)(trans + rA * KTAGS);
            const float4* trB = (const float4*)(trans + rB * KTAGS);
#pragma unroll
            for (int q = 0; q < 12; q++) {
                float4 va = trA[q];
                EA[2 * q]     = pk2(ex2f(va.x * L2E), ex2f(va.y * L2E));
                EA[2 * q + 1] = pk2(ex2f(va.z * L2E), ex2f(va.w * L2E));
                float4 vb4 = trB[q];
                EB[2 * q]     = pk2(ex2f(vb4.x * L2E), ex2f(vb4.y * L2E));
                EB[2 * q + 1] = pk2(ex2f(vb4.z * L2E), ex2f(vb4.w * L2E));
            }
        }

        float aA = eb[rA] + prior[rA];
        float aB = eb[rB] + prior[rB];
        float m0 = __shfl_sync(0xffffffffu, aA, 0);
        float C2 = m0 * L2E;
        float wA = ex2f((aA - m0) * L2E);
        float wB = ex2f((aB - m0) * L2E);
        sv[0][rA] = wA;
        if (hB) sv[0][rB] = wB;
        __syncwarp();
        int p = 0;

        const int Lf = m + 1;   // consume t = 1..m
        float rawA[PF], rawB[PF];
#pragma unroll
        for (int d = 0; d < PF; d++) {
            int t = 1 + d;
            rawA[d] = (t < Lf) ? eb[(size_t)t * KTAGS + rA] : 0.0f;
            rawB[d] = (t < Lf) ? eb[(size_t)t * KTAGS + rB] : 0.0f;
        }

        int t0 = 1;
        // ---- phase 1: branch-free full blocks (all refills in-range) ----
        {
            const float* bA = eb + (size_t)(1 + PF) * KTAGS + rA;
            const float* bBp = eb + (size_t)(1 + PF) * KTAGS + rB;
            for (; t0 + 2 * PF <= Lf; t0 += PF) {
#pragma unroll
                for (int d = 0; d < PF; d++) {
                    float eetA = ex2f(rawA[d] * L2E);
                    float eetB = ex2f(rawB[d] * L2E);
                    rawA[d] = bA[d * KTAGS];
                    rawB[d] = bBp[d * KTAGS];

                    float gA = eetA, gB = eetB;
                    if ((d & 3) == 0) {
                        float r = __shfl_sync(0xffffffffu, wA, 0);
                        float rr = rcpf(r);
                        C2 += lg2f(r);
                        gA = eetA * rr;
                        gB = eetB * rr;
                    }

                    float uA, uB;
                    matvec48(EA, EB, sv[p], uA, uB);
                    wA = uA * gA;
                    wB = uB * gB;

                    const int q2 = p ^ 1;
                    sv[q2][rA] = wA;
                    if (hB) sv[q2][rB] = wB;
                    __syncwarp();
                    p = q2;
                }
                bA += PF * KTAGS;
                bBp += PF * KTAGS;
            }
        }
        // ---- phase 2: predicated tail ----
        for (; t0 < Lf; t0 += PF) {
#pragma unroll
            for (int d = 0; d < PF; d++) {
                const int t = t0 + d;
                if (t >= Lf) break;

                float eetA = ex2f(rawA[d] * L2E);
                float eetB = ex2f(rawB[d] * L2E);
                {
                    int tn = t + PF;
                    rawA[d] = (tn < Lf) ? eb[(size_t)tn * KTAGS + rA] : 0.0f;
                    rawB[d] = (tn < Lf) ? eb[(size_t)tn * KTAGS + rB] : 0.0f;
                }

                float gA = eetA, gB = eetB;
                if ((d & 3) == 0) {
                    float r = __shfl_sync(0xffffffffu, wA, 0);
                    float rr = rcpf(r);
                    C2 += lg2f(r);
                    gA = eetA * rr;
                    gB = eetB * rr;
                }

                float uA, uB;
                matvec48(EA, EB, sv[p], uA, uB);
                wA = uA * gA;
                wB = uB * gB;

                const int q2 = p ^ 1;
                sv[q2][rA] = wA;
                if (hB) sv[q2][rB] = wB;
                __syncwarp();
                p = q2;
            }
        }

        g_wf[b * KTAGS + rA] = wA;
        if (hB) g_wf[b * KTAGS + rB] = wB;
        if (j == 0) g_c2f[b] = C2;

        // ---- path score over full L ----
        const int* tb = tags + (size_t)b * T;
        float acc = 0.0f;
        for (int t = j; t < L; t += 32) {
            int tg = min(max(tb[t], 0), KTAGS - 1);
            float tr = (t == 0) ? prior[tg]
                                : trans[tg * KTAGS + min(max(tb[t - 1], 0), KTAGS - 1)];
            acc += eb[(size_t)t * KTAGS + tg] + tr;
        }
#pragma unroll
        for (int s = 16; s > 0; s >>= 1)
            acc += __shfl_xor_sync(0xffffffffu, acc, s);
        if (j == 0)
            g_path[b] = acc + ftrans[min(max(tb[L - 1], 0), KTAGS - 1)];
    } else {
        // Backward: beta_t = E^T (exp(e_{t+1}) . beta_{t+1})
        unsigned long long EA[24], EB[24];
#pragma unroll
        for (int q = 0; q < 24; q++) {
            int j0 = 2 * q, j1 = 2 * q + 1;
            EA[q] = pk2(ex2f(trans[j0 * KTAGS + rA] * L2E),
                        ex2f(trans[j1 * KTAGS + rA] * L2E));
            EB[q] = pk2(ex2f(trans[j0 * KTAGS + rB] * L2E),
                        ex2f(trans[j1 * KTAGS + rB] * L2E));
        }

        float C2 = 0.0f;
        float vbA, vbB;

        if (m == L - 1) {
            vbA = ex2f(ftrans[rA] * L2E);
            vbB = ex2f(ftrans[rB] * L2E);
        } else {
            float zA = ex2f((ftrans[rA] + eb[(size_t)(L - 1) * KTAGS + rA]) * L2E);
            float zB = ex2f((ftrans[rB] + eb[(size_t)(L - 1) * KTAGS + rB]) * L2E);
            int p = 0;

            const int nsteps = L - 1 - m;
            const int nfull = nsteps - 1;

            float rawA[PF], rawB[PF];
#pragma unroll
            for (int d = 0; d < PF; d++) {
                int t = L - 2 - d;
                rawA[d] = (d < nfull) ? eb[(size_t)t * KTAGS + rA] : 0.0f;
                rawB[d] = (d < nfull) ? eb[(size_t)t * KTAGS + rB] : 0.0f;
            }

            int s0 = 0;
            // ---- phase 1: branch-free full blocks ----
            if (2 * PF <= nfull) {
                const float* bA = eb + (size_t)(L - 2 - PF) * KTAGS + rA;
                const float* bBp = eb + (size_t)(L - 2 - PF) * KTAGS + rB;
                for (; s0 + 2 * PF <= nfull; s0 += PF) {
#pragma unroll
                    for (int d = 0; d < PF; d++) {
                        float eetA = ex2f(rawA[d] * L2E);
                        float eetB = ex2f(rawB[d] * L2E);
                        rawA[d] = *(bA - d * KTAGS);
                        rawB[d] = *(bBp - d * KTAGS);

                        float gA = eetA, gB = eetB;
                        if ((d & 3) == 0) {
                            float r = __shfl_sync(0xffffffffu, zA, 0);
                            float rr = rcpf(r);
                            C2 += lg2f(r);
                            gA = eetA * rr;
                            gB = eetB * rr;
                        }

                        sv[p ^ 1][rA] = zA * gA;
                        if (hB) sv[p ^ 1][rB] = zB * gB;
                        __syncwarp();
                        float uA, uB;
                        matvec48(EA, EB, sv[p ^ 1], uA, uB);
                        zA = uA;
                        zB = uB;
                        p ^= 1;
                    }
                    bA -= PF * KTAGS;
                    bBp -= PF * KTAGS;
                }
            }
            // ---- phase 2: predicated tail ----
            for (; s0 < nfull; s0 += PF) {
#pragma unroll
                for (int d = 0; d < PF; d++) {
                    const int s = s0 + d;
                    if (s >= nfull) break;
                    const int t = L - 2 - s;

                    float eetA = ex2f(rawA[d] * L2E);
                    float eetB = ex2f(rawB[d] * L2E);
                    {
                        int sn = s + PF;
                        int tn = t - PF;
                        rawA[d] = (sn < nfull) ? eb[(size_t)tn * KTAGS + rA] : 0.0f;
                        rawB[d] = (sn < nfull) ? eb[(size_t)tn * KTAGS + rB] : 0.0f;
                    }

                    float gA = eetA, gB = eetB;
                    if ((d & 3) == 0) {
                        float r = __shfl_sync(0xffffffffu, zA, 0);
                        float rr = rcpf(r);
                        C2 += lg2f(r);
                        gA = eetA * rr;
                        gB = eetB * rr;
                    }

                    sv[p ^ 1][rA] = zA * gA;
                    if (hB) sv[p ^ 1][rB] = zB * gB;
                    __syncwarp();
                    float uA, uB;
                    matvec48(EA, EB, sv[p ^ 1], uA, uB);
                    zA = uA;
                    zB = uB;
                    p ^= 1;
                }
            }
            // Final step (t = m): matvec only — operand is raw z (no emission).
            sv[p ^ 1][rA] = zA;
            if (hB) sv[p ^ 1][rB] = zB;
            __syncwarp();
            matvec48(EA, EB, sv[p ^ 1], vbA, vbB);
        }

        g_wb[b * KTAGS + rA] = vbA;
        if (hB) g_wb[b * KTAGS + rB] = vbB;
        if (j == 0) g_c2b[b] = C2;
    }
}

// Parallel combine: 32 blocks x 256 threads, one warp per batch iteration.
__global__ void crf_combine(int B) {
    __shared__ float sh[8];
    const int tid = threadIdx.x;
    const int wid = tid >> 5, j = tid & 31;
    const int gw = blockIdx.x * 8 + wid;
    float v = 0.0f;
    for (int b = gw; b < B; b += 256) {
        float d = g_wf[b * KTAGS + j] * g_wb[b * KTAGS + j];
        if (j < 16) d += g_wf[b * KTAGS + 32 + j] * g_wb[b * KTAGS + 32 + j];
#pragma unroll
        for (int s = 16; s > 0; s >>= 1) d += __shfl_xor_sync(0xffffffffu, d, s);
        if (j == 0)
            v += (lg2f(d) + g_c2f[b] + g_c2b[b]) * LN2 - g_path[b];
    }
    if (j == 0) sh[wid] = v;
    __syncthreads();
    if (tid == 0) {
        float s = 0.0f;
#pragma unroll
        for (int k = 0; k < 8; k++) s += sh[k];
        g_partial[blockIdx.x] = s;
    }
}

__global__ void crf_final(float* __restrict__ out, int B) {
    const int j = threadIdx.x;
    float v = g_partial[j];
#pragma unroll
    for (int s = 16; s > 0; s >>= 1) v += __shfl_xor_sync(0xffffffffu, v, s);
    if (j == 0) out[0] = v / (float)B;
}

extern "C" void kernel_launch(void* const* d_in, const int* in_sizes, int n_in,
                              void* d_out, int out_size) {
    const float* emis    = (const float*)d_in[0];
    const int*   lengths = (const int*)d_in[1];
    const int*   tags    = (const int*)d_in[2];
    const float* prior   = (const float*)d_in[3];
    const float* trans   = (const float*)d_in[4];
    const float* ftrans  = (const float*)d_in[5];

    const int B = in_sizes[1];              // lengths count
    const int T = in_sizes[2] / B;          // tags = [B, T]

    crf_bidir<<<2 * B, 32>>>(emis, lengths, tags, prior, trans, ftrans, B, T);
    crf_combine<<<32, 256>>>(B);
    crf_final<<<1, 32>>>((float*)d_out, B);
}